// round 14
// baseline (speedup 1.0000x reference)
#include <cuda_runtime.h>
#include <cstdint>

#define N_VARS   2048
#define N_LAYERS 8
#define NODES    4096
#define BATCH    8192
#define BT       4              // batch elements per CTA (float4 vector)
#define THREADS  1024
#define NPT      (NODES / THREADS)   // 4
#define NBLK     (NODES / 8)         // 512 8-node blocks per buffer
#define GROUPS   (N_LAYERS * NODES / 8)
#define MAXREF   24
#define COST_INF 0x0fffffffu

// Buffers b=0..7: b=0 holds leaves, b=1..7 hold layer 0..6 outputs.
// Layer l reads buffer l, writes buffer l+1 (layer 7 writes nothing).
// g_P[b*4096+c] in 0..7 = block-local position of node c in buffer b.
__device__ ushort4       g_work [N_LAYERS * NODES];  // masked original children
__device__ ushort4       g_final[N_LAYERS * NODES];  // after sigma remap
__device__ ushort4       g_idx16[N_LAYERS * NODES];  // after slot scheduling
__device__ unsigned char g_P    [N_LAYERS * NODES];
__device__ int           g_cnt  [N_LAYERS * NODES];
__device__ unsigned short g_ref [N_LAYERS * NODES * MAXREF];
__device__ int           g_H    [N_LAYERS * NBLK * 8];   // [b][group][bank]

// ---- A: zero counters/histograms, init P = identity, pack indices ----
__global__ void init_kernel(const int* __restrict__ cidx) {
    int i = blockIdx.x * blockDim.x + threadIdx.x;
    if (i >= N_LAYERS * NODES) return;
    g_cnt[i] = 0;
    g_H[i]   = 0;                      // same element count (8*512*8 = 32768)
    g_P[i]   = (unsigned char)(i & 7); // identity within block
    const int4 p = reinterpret_cast<const int4*>(cidx)[i];
    ushort4 v;
    v.x = (unsigned short)(p.x & (NODES - 1));
    v.y = (unsigned short)(p.y & (NODES - 1));
    v.z = (unsigned short)(p.z & (NODES - 1));
    v.w = (unsigned short)(p.w & (NODES - 1));
    g_work[i] = v;
}

// ---- C: reverse index: child node -> list of reader groups ----
__global__ void reffill_kernel() {
    int i = blockIdx.x * blockDim.x + threadIdx.x;    // (b, reader node n)
    if (i >= N_LAYERS * NODES) return;
    const int b = i >> 12;
    const int n = i & (NODES - 1);
    const unsigned short gid = (unsigned short)(n >> 3);
    const ushort4 v = g_work[i];
    const unsigned short ch[4] = {v.x, v.y, v.z, v.w};
    #pragma unroll
    for (int j = 0; j < 4; j++) {
        const int c = b * NODES + ch[j];
        const int slot = atomicAdd(&g_cnt[c], 1);
        if (slot < MAXREF) g_ref[c * MAXREF + slot] = gid;
    }
}

// ---- zero H (between Jacobi iterations) ----
__global__ void zeroH_kernel() {
    int i = blockIdx.x * blockDim.x + threadIdx.x;
    if (i < N_LAYERS * NBLK * 8) g_H[i] = 0;
}

// ---- E: per-group bank histograms under current P ----
__global__ void buildH_kernel() {
    int i = blockIdx.x * blockDim.x + threadIdx.x;    // (b, reader node n)
    if (i >= N_LAYERS * NODES) return;
    const int b = i >> 12;
    const int n = i & (NODES - 1);
    const int g = n >> 3;
    const ushort4 v = g_work[i];
    const unsigned short ch[4] = {v.x, v.y, v.z, v.w};
    #pragma unroll
    for (int j = 0; j < 4; j++) {
        const int bank = (int)g_P[b * NODES + ch[j]];
        atomicAdd(&g_H[(b * NBLK + g) * 8 + bank], 1);
    }
}

// ---- F: Jacobi block update, one warp per (buffer, block) ----
__global__ void updateP_kernel() {
    const int w    = (blockIdx.x * blockDim.x + threadIdx.x) >> 5;
    const int lane = threadIdx.x & 31;
    if (w >= N_LAYERS * NBLK) return;
    const int b   = w >> 9;
    const int blk = w & (NBLK - 1);

    unsigned int taken = 0;
    for (int i = 0; i < 8; i++) {
        const int c  = b * NODES + blk * 8 + i;
        int cn = g_cnt[c]; if (cn > MAXREF) cn = MAXREF;
        const int old = (int)g_P[c];

        unsigned int cost = COST_INF;
        if (lane < 8 && !((taken >> lane) & 1u)) {
            cost = 0;
            for (int r = 0; r < cn; r++) {
                const int g = (int)g_ref[c * MAXREF + r];
                int h = g_H[(b * NBLK + g) * 8 + lane] - ((lane == old) ? 1 : 0);
                if (h < 0) h = 0;
                cost += (h >= 10) ? (1u << 20) : (1u << (2 * h));
            }
        }
        unsigned int key = (cost << 3) | (unsigned int)(lane & 7);
        if (lane >= 8) key = 0xffffffffu;
        #pragma unroll
        for (int off = 16; off > 0; off >>= 1) {
            const unsigned int o = __shfl_xor_sync(0xffffffffu, key, off);
            key = (o < key) ? o : key;
        }
        const unsigned int bank = key & 7u;
        taken |= (1u << bank);
        if (lane == 0) g_P[c] = (unsigned char)bank;
    }
}

// ---- G: build final table: position-ordered rows, children remapped ----
__global__ void remap_kernel() {
    int i = blockIdx.x * blockDim.x + threadIdx.x;    // (l, position p)
    if (i >= N_LAYERS * NODES) return;
    const int l = i >> 12;
    const int p = i & (NODES - 1);
    int n = p;
    if (l < 7) {
        // node n in p's block whose output position P[l+1][n] == p&7
        const int base = p & ~7;
        const int t = p & 7;
        for (int k = 0; k < 8; k++) {
            if ((int)g_P[(l + 1) * NODES + base + k] == t) { n = base + k; break; }
        }
    }
    const ushort4 v = g_work[l * NODES + n];
    ushort4 o;
    o.x = (unsigned short)((v.x & ~7) | g_P[l * NODES + v.x]);
    o.y = (unsigned short)((v.y & ~7) | g_P[l * NODES + v.y]);
    o.z = (unsigned short)((v.z & ~7) | g_P[l * NODES + v.z]);
    o.w = (unsigned short)((v.w & ~7) | g_P[l * NODES + v.w]);
    g_final[i] = o;
}

// ---- slot scheduler (proven R11 warp-greedy), input g_final ----
__device__ const unsigned char PERM24[24][4] = {
    {0,1,2,3},{0,1,3,2},{0,2,1,3},{0,2,3,1},{0,3,1,2},{0,3,2,1},
    {1,0,2,3},{1,0,3,2},{1,2,0,3},{1,2,3,0},{1,3,0,2},{1,3,2,0},
    {2,0,1,3},{2,0,3,1},{2,1,0,3},{2,1,3,0},{2,3,0,1},{2,3,1,0},
    {3,0,1,2},{3,0,2,1},{3,1,0,2},{3,1,2,0},{3,2,0,1},{3,2,1,0}
};

__global__ void sched_kernel() {
    const int gwarp = (blockIdx.x * blockDim.x + threadIdx.x) >> 5;
    const int lane  = threadIdx.x & 31;
    if (gwarp >= GROUPS) return;

    unsigned long long my_ch = 0;
    unsigned int my_banks = 0;
    if (lane < 8) {
        const ushort4 v = g_final[gwarp * 8 + lane];
        my_ch = (unsigned long long)v.x | ((unsigned long long)v.y << 16)
              | ((unsigned long long)v.z << 32) | ((unsigned long long)v.w << 48);
        my_banks = (v.x & 7) | ((v.y & 7) << 3) | ((v.z & 7) << 6) | ((v.w & 7) << 9);
    }
    unsigned int permw = 0;
    if (lane < 24) {
        permw = (unsigned int)PERM24[lane][0]
              | ((unsigned int)PERM24[lane][1] << 8)
              | ((unsigned int)PERM24[lane][2] << 16)
              | ((unsigned int)PERM24[lane][3] << 24);
    }
    unsigned int h0 = 0, h1 = 0, h2 = 0, h3 = 0;
    unsigned int my_wperm = 0;

    for (int n = 0; n < 8; n++) {
        const unsigned int bankw = __shfl_sync(0xffffffffu, my_banks, n);
        unsigned int cost = 0x00ffffffu;
        if (lane < 24) {
            cost = 0;
            { const int sel = (int)( permw        & 255u); const int b = (bankw >> (sel * 3)) & 7; const int h = (h0 >> (b * 4)) & 15; cost += 1u << (2 * h); }
            { const int sel = (int)((permw >> 8)  & 255u); const int b = (bankw >> (sel * 3)) & 7; const int h = (h1 >> (b * 4)) & 15; cost += 1u << (2 * h); }
            { const int sel = (int)((permw >> 16) & 255u); const int b = (bankw >> (sel * 3)) & 7; const int h = (h2 >> (b * 4)) & 15; cost += 1u << (2 * h); }
            { const int sel = (int)((permw >> 24) & 255u); const int b = (bankw >> (sel * 3)) & 7; const int h = (h3 >> (b * 4)) & 15; cost += 1u << (2 * h); }
        }
        unsigned int key = (cost << 8) | (unsigned int)lane;
        #pragma unroll
        for (int off = 16; off > 0; off >>= 1) {
            const unsigned int o = __shfl_xor_sync(0xffffffffu, key, off);
            key = (o < key) ? o : key;
        }
        const unsigned int wperm = __shfl_sync(0xffffffffu, permw, (int)(key & 255u));
        if (lane == n) my_wperm = wperm;
        { const int sel = (int)( wperm        & 255u); const int b = (bankw >> (sel * 3)) & 7; h0 += 1u << (b * 4); }
        { const int sel = (int)((wperm >> 8)  & 255u); const int b = (bankw >> (sel * 3)) & 7; h1 += 1u << (b * 4); }
        { const int sel = (int)((wperm >> 16) & 255u); const int b = (bankw >> (sel * 3)) & 7; h2 += 1u << (b * 4); }
        { const int sel = (int)((wperm >> 24) & 255u); const int b = (bankw >> (sel * 3)) & 7; h3 += 1u << (b * 4); }
    }
    if (lane < 8) {
        const int s0 = (int)( my_wperm        & 255u);
        const int s1 = (int)((my_wperm >> 8)  & 255u);
        const int s2 = (int)((my_wperm >> 16) & 255u);
        const int s3 = (int)((my_wperm >> 24) & 255u);
        ushort4 w;
        w.x = (unsigned short)((my_ch >> (s0 * 16)) & 0xffffu);
        w.y = (unsigned short)((my_ch >> (s1 * 16)) & 0xffffu);
        w.z = (unsigned short)((my_ch >> (s2 * 16)) & 0xffffu);
        w.w = (unsigned short)((my_ch >> (s3 * 16)) & 0xffffu);
        g_idx16[gwarp * 8 + lane] = w;
    }
}

// ---- main SPN kernel ----
extern __shared__ float4 s_buf[];   // [2 * NODES] float4 = 128 KB

__global__ __launch_bounds__(THREADS, 1)
void spn_kernel(const float* __restrict__ x,
                const unsigned char* __restrict__ marg,
                float* __restrict__ out) {
    float4* buf0 = s_buf;
    float4* buf1 = s_buf + NODES;

    const int tid = threadIdx.x;
    const int b0  = blockIdx.x * BT;

    // Leaves placed through buffer-0 permutation.
    for (int j = tid; j < N_VARS; j += THREADS) {
        const bool m = (marg[j] != 0);
        float4 v;
        v.x = x[(size_t)(b0 + 0) * N_VARS + j];
        v.y = x[(size_t)(b0 + 1) * N_VARS + j];
        v.z = x[(size_t)(b0 + 2) * N_VARS + j];
        v.w = x[(size_t)(b0 + 3) * N_VARS + j];
        float4 w1, w2;
        if (m) {
            w1 = make_float4(1.f, 1.f, 1.f, 1.f);
            w2 = make_float4(1.f, 1.f, 1.f, 1.f);
        } else {
            w1 = v;
            w2 = make_float4(1.f - v.x, 1.f - v.y, 1.f - v.z, 1.f - v.w);
        }
        const int j2 = j + N_VARS;
        buf0[(j  & ~7) | g_P[j ]] = w1;
        buf0[(j2 & ~7) | g_P[j2]] = w2;
    }
    __syncthreads();

    float4* cur = buf0;
    float4* nxt = buf1;
    float4  acc = make_float4(0.f, 0.f, 0.f, 0.f);

    #pragma unroll
    for (int l = 0; l < N_LAYERS; l++) {
        const ushort4* __restrict__ idxL = g_idx16 + l * NODES;
        ushort4 c[NPT];
        #pragma unroll
        for (int i = 0; i < NPT; i++) c[i] = idxL[tid + i * THREADS];

        #pragma unroll
        for (int i = 0; i < NPT; i++) {
            const int node = tid + i * THREADS;
            const float4 a = cur[c[i].x];
            const float4 b = cur[c[i].y];
            const float4 d = cur[c[i].z];
            const float4 e = cur[c[i].w];
            float4 r;
            if ((l & 1) == 0) {
                r.x = a.x * b.x * d.x * e.x;
                r.y = a.y * b.y * d.y * e.y;
                r.z = a.z * b.z * d.z * e.z;
                r.w = a.w * b.w * d.w * e.w;
            } else {
                r.x = a.x + b.x + d.x + e.x;
                r.y = a.y + b.y + d.y + e.y;
                r.z = a.z + b.z + d.z + e.z;
                r.w = a.w + b.w + d.w + e.w;
            }
            if (l == N_LAYERS - 1) {
                acc.x += r.x; acc.y += r.y; acc.z += r.z; acc.w += r.w;
            } else {
                nxt[node] = r;
            }
        }
        if (l < N_LAYERS - 1) __syncthreads();
        float4* t = cur; cur = nxt; nxt = t;
    }

    #pragma unroll
    for (int off = 16; off > 0; off >>= 1) {
        acc.x += __shfl_down_sync(0xffffffffu, acc.x, off);
        acc.y += __shfl_down_sync(0xffffffffu, acc.y, off);
        acc.z += __shfl_down_sync(0xffffffffu, acc.z, off);
        acc.w += __shfl_down_sync(0xffffffffu, acc.w, off);
    }
    __shared__ float4 warp_sums[THREADS / 32];
    const int wid  = tid >> 5;
    const int lane = tid & 31;
    if (lane == 0) warp_sums[wid] = acc;
    __syncthreads();
    if (wid == 0) {
        float4 s = (lane < THREADS / 32) ? warp_sums[lane]
                                         : make_float4(0.f, 0.f, 0.f, 0.f);
        #pragma unroll
        for (int off = 16; off > 0; off >>= 1) {
            s.x += __shfl_down_sync(0xffffffffu, s.x, off);
            s.y += __shfl_down_sync(0xffffffffu, s.y, off);
            s.z += __shfl_down_sync(0xffffffffu, s.z, off);
            s.w += __shfl_down_sync(0xffffffffu, s.w, off);
        }
        if (lane == 0) *reinterpret_cast<float4*>(out + b0) = s;
    }
}

extern "C" void kernel_launch(void* const* d_in, const int* in_sizes, int n_in,
                              void* d_out, int out_size) {
    const float*         x    = (const float*)d_in[0];
    const unsigned char* marg = (const unsigned char*)d_in[1];
    const int*           cidx = (const int*)d_in[2];
    float*               out  = (float*)d_out;

    cudaFuncSetAttribute(spn_kernel,
                         cudaFuncAttributeMaxDynamicSharedMemorySize,
                         2 * NODES * (int)sizeof(float4));

    const int tpb = 256;
    const int n32k = (N_LAYERS * NODES + tpb - 1) / tpb;          // 128 blocks
    const int nwrp = (N_LAYERS * NBLK * 32 + tpb - 1) / tpb;      // 512 blocks

    init_kernel<<<n32k, tpb>>>(cidx);        // zero cnt/H, P=identity, pack
    reffill_kernel<<<n32k, tpb>>>();         // reverse index child->groups
    buildH_kernel<<<n32k, tpb>>>();          // H under identity P
    updateP_kernel<<<nwrp, tpb>>>();         // Jacobi iter 1
    zeroH_kernel<<<n32k, tpb>>>();
    buildH_kernel<<<n32k, tpb>>>();          // H under updated P
    updateP_kernel<<<nwrp, tpb>>>();         // Jacobi iter 2
    remap_kernel<<<n32k, tpb>>>();           // position-ordered, remapped table
    sched_kernel<<<nwrp, tpb>>>();           // slot permutations (R11 greedy)

    spn_kernel<<<BATCH / BT, THREADS, 2 * NODES * (int)sizeof(float4)>>>(x, marg, out);
}